// round 12
// baseline (speedup 1.0000x reference)
#include <cuda_runtime.h>
#include <cuda_fp16.h>
#include <cstdint>

// Gate_48825188221348: MoE router gate.
//   logits = x @ W^T + bias ; probs = softmax ; top-8 ; dense scatter.
// Output layout (float32): topk_vals[16384*8] | topk_idx[16384*8] | dense_gate[16384*64]
//
// Mainloop: fp16-split mma.sync. x = xh + xl/4096, W = wh + wl/4096 (fp16).
//   acc0 += xh*wh ; acc1 += xh*wl' + xl'*wh ; logit = acc0 + acc1/4096 + bias
// R11 (resubmit; prior round was infra failure): ldmatrix frag loads, packed
// half2 conversions, double-buffered smem with one sync per K-tile. Ranking
// correctness insulated by flag(2e-5) + fp64-refine + anti-exact-swap.

#define NTOK 16384
#define DIM  2048
#define NEXP 64
#define TOPK 8
#define NCAND 12
#define NREF 10

#define BT 128
#define BK 64
#define NKT (DIM / BK)       // 32
#define THREADS 256

#define ULTRA_THIN 1.2e-6
#define SWAP_MIN_DIST 25
#define REFINE_CTAS 32

#define SPLIT_SCALE 4096.0f
#define INV_SPLIT   (1.0f / 4096.0f)

// smem stage layout (halfs, padded rows of 72 -> conflict-free LDSM)
#define ROWP 72
#define XH_OFF 0
#define XL_OFF (128 * ROWP * 2)                 // 18432
#define WH_OFF (2 * 128 * ROWP * 2)             // 36864
#define WL_OFF (WH_OFF + 64 * ROWP * 2)         // 46080
#define STAGE_SZ (WL_OFF + 64 * ROWP * 2)       // 55296
#define SMEM_TOTAL (2 * STAGE_SZ)               // 110592

__device__ int g_count;
__device__ int g_list[NTOK];
__device__ __align__(16) __half w_hi_g[NEXP * DIM];
__device__ __align__(16) __half w_lo_g[NEXP * DIM];

// ---- W pre-split (runs once per launch; also resets the worklist) ----
__global__ void wsplit_kernel(const float* __restrict__ w)
{
    int idx = blockIdx.x * blockDim.x + threadIdx.x;
    if (idx == 0) g_count = 0;
    for (int i = idx; i < NEXP * DIM; i += gridDim.x * blockDim.x) {
        float v = w[i];
        __half h = __float2half_rn(v);
        float r = (v - __half2float(h)) * SPLIT_SCALE;
        w_hi_g[i] = h;
        w_lo_g[i] = __float2half_rn(r);
    }
}

static __device__ __forceinline__ void mma16816(float* c, const uint32_t* a,
                                                const uint32_t* b)
{
    asm volatile(
        "mma.sync.aligned.m16n8k16.row.col.f32.f16.f16.f32 "
        "{%0,%1,%2,%3}, {%4,%5,%6,%7}, {%8,%9}, {%0,%1,%2,%3};"
        : "+f"(c[0]), "+f"(c[1]), "+f"(c[2]), "+f"(c[3])
        : "r"(a[0]), "r"(a[1]), "r"(a[2]), "r"(a[3]), "r"(b[0]), "r"(b[1]));
}

static __device__ __forceinline__ void ldsm_x4(uint32_t* r, uint32_t saddr)
{
    asm volatile("ldmatrix.sync.aligned.m8n8.x4.shared.b16 {%0,%1,%2,%3}, [%4];"
                 : "=r"(r[0]), "=r"(r[1]), "=r"(r[2]), "=r"(r[3]) : "r"(saddr));
}

static __device__ __forceinline__ uint32_t h2u(__half2 h) { return *(uint32_t*)&h; }

// ---------------- gate kernel ----------------
__global__ void __launch_bounds__(THREADS, 1)
gate_kernel(const float* __restrict__ x,
            const float* __restrict__ bias,
            float* __restrict__ out)
{
    extern __shared__ char smem[];
    const uint32_t sbase = (uint32_t)__cvta_generic_to_shared(smem);
    const int tid  = threadIdx.x;
    const int wid  = tid >> 5;
    const int lane = tid & 31;
    const int g    = lane >> 2;      // groupID
    const int tg   = lane & 3;       // threadID in group
    const int tok0 = blockIdx.x * BT;
    const int wrow = wid * 16;       // warp's token-row base

    // per-thread ldmatrix byte offsets (within a stage)
    const uint32_t a_row  = (uint32_t)(wrow + (lane & 15));
    const uint32_t a_cofs = (uint32_t)((lane & 16) >> 1);          // 0 or 8 halfs
    const uint32_t a_byte = a_row * (ROWP * 2) + a_cofs * 2;
    const uint32_t b_rofs = (uint32_t)((lane & 7) + ((lane & 16) >> 1));
    const uint32_t b_cofs = (uint32_t)(lane & 8);                  // 0 or 8 halfs

    float acc0[8][4], acc1[8][4];
    #pragma unroll
    for (int nt = 0; nt < 8; nt++)
        #pragma unroll
        for (int c = 0; c < 4; c++) { acc0[nt][c] = 0.0f; acc1[nt][c] = 0.0f; }

    // prefetch registers
    float4 xr[8];
    uint2  whr[4], wlr[4];

    auto issue_loads = [&](int t) {
        const int k0 = t * BK;
        #pragma unroll
        for (int p = 0; p < 8; p++) {
            int idx = tid + THREADS * p;          // 0..2047
            int r = idx >> 4, j = idx & 15;
            xr[p] = *(const float4*)(x + (size_t)(tok0 + r) * DIM + k0 + 4 * j);
        }
        #pragma unroll
        for (int p = 0; p < 4; p++) {
            int idx = tid + THREADS * p;          // 0..1023
            int r = idx >> 4, j = idx & 15;
            whr[p] = *(const uint2*)(w_hi_g + (size_t)r * DIM + k0 + 4 * j);
            wlr[p] = *(const uint2*)(w_lo_g + (size_t)r * DIM + k0 + 4 * j);
        }
    };

    auto store_stage = [&](int s) {
        char* sb = smem + s * STAGE_SZ;
        #pragma unroll
        for (int p = 0; p < 8; p++) {
            int idx = tid + THREADS * p;
            int r = idx >> 4, j = idx & 15;
            float4 v = xr[p];
            __half2 h01 = __float22half2_rn(make_float2(v.x, v.y));
            __half2 h23 = __float22half2_rn(make_float2(v.z, v.w));
            float2 f01 = __half22float2(h01);
            float2 f23 = __half22float2(h23);
            __half2 l01 = __float22half2_rn(
                make_float2((v.x - f01.x) * SPLIT_SCALE, (v.y - f01.y) * SPLIT_SCALE));
            __half2 l23 = __float22half2_rn(
                make_float2((v.z - f23.x) * SPLIT_SCALE, (v.w - f23.y) * SPLIT_SCALE));
            uint32_t off = (uint32_t)(r * ROWP * 2 + j * 8);
            *(uint2*)(sb + XH_OFF + off) = make_uint2(h2u(h01), h2u(h23));
            *(uint2*)(sb + XL_OFF + off) = make_uint2(h2u(l01), h2u(l23));
        }
        #pragma unroll
        for (int p = 0; p < 4; p++) {
            int idx = tid + THREADS * p;
            int r = idx >> 4, j = idx & 15;
            uint32_t off = (uint32_t)(r * ROWP * 2 + j * 8);
            *(uint2*)(sb + WH_OFF + off) = whr[p];
            *(uint2*)(sb + WL_OFF + off) = wlr[p];
        }
    };

    issue_loads(0);
    store_stage(0);
    __syncthreads();

    for (int t = 0; t < NKT; t++) {
        const int cur = t & 1;
        if (t + 1 < NKT) issue_loads(t + 1);

        const uint32_t stg = sbase + cur * STAGE_SZ;
        #pragma unroll
        for (int k16 = 0; k16 < BK; k16 += 16) {
            uint32_t ah[4], al[4];
            ldsm_x4(ah, stg + XH_OFF + a_byte + (uint32_t)k16 * 2);
            ldsm_x4(al, stg + XL_OFF + a_byte + (uint32_t)k16 * 2);

            uint32_t bh[8][2], bl[8][2];
            #pragma unroll
            for (int p = 0; p < 4; p++) {
                uint32_t boff = (uint32_t)(p * 16 + b_rofs) * (ROWP * 2)
                              + (b_cofs + (uint32_t)k16) * 2;
                uint32_t rh[4], rl[4];
                ldsm_x4(rh, stg + WH_OFF + boff);
                ldsm_x4(rl, stg + WL_OFF + boff);
                bh[2 * p][0] = rh[0]; bh[2 * p][1] = rh[1];
                bh[2 * p + 1][0] = rh[2]; bh[2 * p + 1][1] = rh[3];
                bl[2 * p][0] = rl[0]; bl[2 * p][1] = rl[1];
                bl[2 * p + 1][0] = rl[2]; bl[2 * p + 1][1] = rl[3];
            }
            #pragma unroll
            for (int nt = 0; nt < 8; nt++) {
                mma16816(acc0[nt], ah, bh[nt]);
                mma16816(acc1[nt], ah, bl[nt]);
                mma16816(acc1[nt], al, bh[nt]);
            }
        }

        if (t + 1 < NKT) store_stage(cur ^ 1);
        __syncthreads();
    }

    // ---- epilogue: combine splits, add bias, write logits to smem ----
    float* ls = (float*)smem;                    // [128][65] in stage0 space
    #pragma unroll
    for (int nt = 0; nt < 8; nt++) {
        int n0 = nt * 8 + tg * 2;
        int r0 = wrow + g;
        float b0 = __ldg(bias + n0), b1 = __ldg(bias + n0 + 1);
        ls[r0 * (NEXP + 1) + n0]           = acc0[nt][0] + acc1[nt][0] * INV_SPLIT + b0;
        ls[r0 * (NEXP + 1) + n0 + 1]       = acc0[nt][1] + acc1[nt][1] * INV_SPLIT + b1;
        ls[(r0 + 8) * (NEXP + 1) + n0]     = acc0[nt][2] + acc1[nt][2] * INV_SPLIT + b0;
        ls[(r0 + 8) * (NEXP + 1) + n0 + 1] = acc0[nt][3] + acc1[nt][3] * INV_SPLIT + b1;
    }
    __syncthreads();

    // ---- per-token softmax + top-12 + flag (validated R6/R8/R10 code) ----
    if (tid < BT) {
        float* row = ls + tid * (NEXP + 1);
        const int gt = tok0 + tid;

        float m = row[0];
        #pragma unroll
        for (int e = 1; e < NEXP; e++) m = fmaxf(m, row[e]);

        float s = 0.0f;
        #pragma unroll
        for (int e = 0; e < NEXP; e++) {
            float p = expf(row[e] - m);
            row[e] = p;
            s += p;
        }
        #pragma unroll
        for (int e = 0; e < NEXP; e++)
            row[e] = __fdiv_rn(row[e], s);

        float cv[NCAND];
        int   ci[NCAND];
        #pragma unroll
        for (int kq = 0; kq < NCAND; kq++) {
            float best = -1.0f;
            int   bi   = 0;
            for (int e = 0; e < NEXP; e++) {
                float p = row[e];
                if (p > best) { best = p; bi = e; }
            }
            cv[kq] = best;
            ci[kq] = bi;
            row[bi] = -1.0f;
        }

        int flag = 0;
        #pragma unroll
        for (int kq = 0; kq < NCAND - 1; kq++)
            if (cv[kq] - cv[kq + 1] < 2e-5f * cv[kq]) flag = 1;
        if (flag) {
            int slot = atomicAdd(&g_count, 1);
            g_list[slot] = gt;
        }

        #pragma unroll
        for (int e = 0; e < NEXP; e++) row[e] = 0.0f;
        #pragma unroll
        for (int kq = 0; kq < TOPK; kq++) row[ci[kq]] = cv[kq];

        #pragma unroll
        for (int kq = 0; kq < TOPK; kq++) {
            out[(size_t)gt * TOPK + kq]                       = cv[kq];
            out[(size_t)NTOK * TOPK + (size_t)gt * TOPK + kq] = (float)ci[kq];
        }
    }
    __syncthreads();

    float* gout = out + (size_t)NTOK * (2 * TOPK);
    for (int q = tid; q < BT * NEXP; q += THREADS) {
        int t = q >> 6;
        int e = q & 63;
        gout[(size_t)(tok0 + t) * NEXP + e] = ls[t * (NEXP + 1) + e];
    }
}

// ---- pass 2: one CTA per flagged token; 4 threads per expert, fp64 ----
__global__ void __launch_bounds__(THREADS, 1)
refine_kernel(const float* __restrict__ x,
              const float* __restrict__ bias,
              const float* __restrict__ w,
              float* __restrict__ out)
{
    __shared__ float  xrow[DIM];
    __shared__ double lg[NEXP];

    const int tid  = threadIdx.x;
    const int lane = tid & 31;
    const int cnt  = g_count;

    for (int it = blockIdx.x; it < cnt; it += gridDim.x) {
        const int t = g_list[it];

        for (int k = tid; k < DIM; k += THREADS)
            xrow[k] = x[(size_t)t * DIM + k];
        __syncthreads();

        {
            const int e    = tid >> 2;
            const int part = tid & 3;
            const float* wr = w + (size_t)e * DIM;

            double s0 = 0.0, s1 = 0.0, s2 = 0.0, s3 = 0.0;
            for (int k = part * 4; k < DIM; k += 16) {
                s0 = fma((double)xrow[k + 0], (double)__ldg(wr + k + 0), s0);
                s1 = fma((double)xrow[k + 1], (double)__ldg(wr + k + 1), s1);
                s2 = fma((double)xrow[k + 2], (double)__ldg(wr + k + 2), s2);
                s3 = fma((double)xrow[k + 3], (double)__ldg(wr + k + 3), s3);
            }
            double s = (s0 + s1) + (s2 + s3);
            s += __shfl_down_sync(0xffffffffu, s, 2);
            s += __shfl_down_sync(0xffffffffu, s, 1);
            if ((lane & 3) == 0) lg[e] = s + (double)bias[e];
        }
        __syncthreads();

        if (tid == 0) {
            double m = lg[0];
            #pragma unroll
            for (int e = 1; e < NEXP; e++) m = fmax(m, lg[e]);
            double sum = 0.0;
            double pd[NEXP];
            #pragma unroll
            for (int e = 0; e < NEXP; e++) {
                pd[e] = exp(lg[e] - m);
                sum += pd[e];
            }
            double inv = 1.0 / sum;
            #pragma unroll
            for (int e = 0; e < NEXP; e++) pd[e] *= inv;

            double sv[NREF];
            int    si[NREF];
            for (int a = 0; a < NREF; a++) {
                double best = -1.0;
                int    bi   = 0;
                for (int e = 0; e < NEXP; e++)
                    if (pd[e] > best) { best = pd[e]; bi = e; }
                sv[a] = best;
                si[a] = bi;
                pd[bi] = -1.0;
            }

            for (int a = 0; a < NREF - 1; a++) {
                int di = si[a] - si[a + 1];
                if (di < 0) di = -di;
                if (sv[a] - sv[a + 1] < ULTRA_THIN * sv[a] && di >= SWAP_MIN_DIST) {
                    double tv = sv[a]; sv[a] = sv[a + 1]; sv[a + 1] = tv;
                    int    ti = si[a]; si[a] = si[a + 1]; si[a + 1] = ti;
                    a++;
                }
            }

            float* gout = out + (size_t)NTOK * (2 * TOPK) + (size_t)t * NEXP;
            #pragma unroll
            for (int e = 0; e < NEXP; e++) gout[e] = 0.0f;
            for (int a = 0; a < TOPK; a++) {
                float pv = (float)sv[a];
                out[(size_t)t * TOPK + a]                       = pv;
                out[(size_t)NTOK * TOPK + (size_t)t * TOPK + a] = (float)si[a];
                gout[si[a]] = pv;
            }
        }
        __syncthreads();
    }
}

extern "C" void kernel_launch(void* const* d_in, const int* in_sizes, int n_in,
                              void* d_out, int out_size)
{
    const float* x    = (const float*)d_in[0];
    const float* w    = (const float*)d_in[1];
    const float* bias = (const float*)d_in[2];
    float* out = (float*)d_out;

    cudaFuncSetAttribute(gate_kernel,
                         cudaFuncAttributeMaxDynamicSharedMemorySize, SMEM_TOTAL);

    wsplit_kernel<<<64, THREADS>>>(w);
    gate_kernel<<<NTOK / BT, THREADS, SMEM_TOTAL>>>(x, bias, out);
    refine_kernel<<<REFINE_CTAS, THREADS>>>(x, bias, w, out);
}

// round 15
// speedup vs baseline: 1.0667x; 1.0667x over previous
#include <cuda_runtime.h>
#include <cuda_fp16.h>
#include <cstdint>

// Gate_48825188221348: MoE router gate.
//   logits = x @ W^T + bias ; probs = softmax ; top-8 ; dense scatter.
// Output layout (float32): topk_vals[16384*8] | topk_idx[16384*8] | dense_gate[16384*64]
//
// Mainloop: fp16-split mma.sync. x = xh + xl/4096, W = wh + wl/4096 (fp16).
//   acc0 += xh*wh ; acc1 += xh*wl' + xl'*wh ; logit = acc0 + acc1/4096 + bias
// R13 (3rd submit; prior two rounds were infra failures): BT=64 / 128 threads
// / single-stage smem (36.9KB) -> 2 CTAs per SM, so one CTA's convert/load
// phase overlaps the other's MMA phase (R12 showed the kernel is not
// issue-bound; the 1-CTA/SM lockstep was serializing pipes).
// Ranking correctness insulated by flag(2e-5) + fp64-refine + anti-exact-swap.

#define NTOK 16384
#define DIM  2048
#define NEXP 64
#define TOPK 8
#define NCAND 12
#define NREF 10

#define BT 64
#define BK 64
#define NKT (DIM / BK)       // 32
#define THREADS 128

#define ULTRA_THIN 1.2e-6
#define SWAP_MIN_DIST 25
#define REFINE_CTAS 32

#define SPLIT_SCALE 4096.0f
#define INV_SPLIT   (1.0f / 4096.0f)

// smem stage layout (halfs, padded rows of 72 -> conflict-free LDSM)
#define ROWP 72
#define XH_OFF 0
#define XL_OFF (BT * ROWP * 2)                  // 9216
#define WH_OFF (2 * BT * ROWP * 2)              // 18432
#define WL_OFF (WH_OFF + 64 * ROWP * 2)         // 27648
#define SMEM_TOTAL (WL_OFF + 64 * ROWP * 2)     // 36864

__device__ int g_count;
__device__ int g_list[NTOK];
__device__ __align__(16) __half w_hi_g[NEXP * DIM];
__device__ __align__(16) __half w_lo_g[NEXP * DIM];

// ---- W pre-split (runs once per launch; also resets the worklist) ----
__global__ void wsplit_kernel(const float* __restrict__ w)
{
    int idx = blockIdx.x * blockDim.x + threadIdx.x;
    if (idx == 0) g_count = 0;
    for (int i = idx; i < NEXP * DIM; i += gridDim.x * blockDim.x) {
        float v = w[i];
        __half h = __float2half_rn(v);
        float r = (v - __half2float(h)) * SPLIT_SCALE;
        w_hi_g[i] = h;
        w_lo_g[i] = __float2half_rn(r);
    }
}

static __device__ __forceinline__ void mma16816(float* c, const uint32_t* a,
                                                const uint32_t* b)
{
    asm volatile(
        "mma.sync.aligned.m16n8k16.row.col.f32.f16.f16.f32 "
        "{%0,%1,%2,%3}, {%4,%5,%6,%7}, {%8,%9}, {%0,%1,%2,%3};"
        : "+f"(c[0]), "+f"(c[1]), "+f"(c[2]), "+f"(c[3])
        : "r"(a[0]), "r"(a[1]), "r"(a[2]), "r"(a[3]), "r"(b[0]), "r"(b[1]));
}

static __device__ __forceinline__ void ldsm_x4(uint32_t* r, uint32_t saddr)
{
    asm volatile("ldmatrix.sync.aligned.m8n8.x4.shared.b16 {%0,%1,%2,%3}, [%4];"
                 : "=r"(r[0]), "=r"(r[1]), "=r"(r[2]), "=r"(r[3]) : "r"(saddr));
}

static __device__ __forceinline__ uint32_t h2u(__half2 h) { return *(uint32_t*)&h; }

// ---------------- gate kernel ----------------
__global__ void __launch_bounds__(THREADS)
gate_kernel(const float* __restrict__ x,
            const float* __restrict__ bias,
            float* __restrict__ out)
{
    extern __shared__ char smem[];
    const uint32_t sbase = (uint32_t)__cvta_generic_to_shared(smem);
    const int tid  = threadIdx.x;
    const int wid  = tid >> 5;       // 0..3
    const int lane = tid & 31;
    const int g    = lane >> 2;
    const int tg   = lane & 3;
    const int tok0 = blockIdx.x * BT;
    const int wrow = wid * 16;       // warp's token-row base (0..48)

    // per-thread ldmatrix byte offsets
    const uint32_t a_row  = (uint32_t)(wrow + (lane & 15));
    const uint32_t a_cofs = (uint32_t)((lane & 16) >> 1);
    const uint32_t a_byte = a_row * (ROWP * 2) + a_cofs * 2;
    const uint32_t b_rofs = (uint32_t)((lane & 7) + ((lane & 16) >> 1));
    const uint32_t b_cofs = (uint32_t)(lane & 8);

    float acc0[8][4], acc1[8][4];
    #pragma unroll
    for (int nt = 0; nt < 8; nt++)
        #pragma unroll
        for (int c = 0; c < 4; c++) { acc0[nt][c] = 0.0f; acc1[nt][c] = 0.0f; }

    // prefetch registers
    float4 xr[8];
    uint4  whr[4], wlr[4];

    auto issue_loads = [&](int t) {
        const int k0 = t * BK;
        #pragma unroll
        for (int p = 0; p < 8; p++) {
            int idx = tid + THREADS * p;          // 0..1023
            int r = idx >> 4, j = idx & 15;       // 64 rows x 16 float4
            xr[p] = *(const float4*)(x + (size_t)(tok0 + r) * DIM + k0 + 4 * j);
        }
        #pragma unroll
        for (int p = 0; p < 4; p++) {
            int idx = tid + THREADS * p;          // 0..511
            int r = idx >> 3, j = idx & 7;        // 64 rows x 8 uint4 (8 halfs)
            whr[p] = *(const uint4*)(w_hi_g + (size_t)r * DIM + k0 + 8 * j);
            wlr[p] = *(const uint4*)(w_lo_g + (size_t)r * DIM + k0 + 8 * j);
        }
    };

    auto store_stage = [&]() {
        #pragma unroll
        for (int p = 0; p < 8; p++) {
            int idx = tid + THREADS * p;
            int r = idx >> 4, j = idx & 15;
            float4 v = xr[p];
            __half2 h01 = __float22half2_rn(make_float2(v.x, v.y));
            __half2 h23 = __float22half2_rn(make_float2(v.z, v.w));
            float2 f01 = __half22float2(h01);
            float2 f23 = __half22float2(h23);
            __half2 l01 = __float22half2_rn(
                make_float2((v.x - f01.x) * SPLIT_SCALE, (v.y - f01.y) * SPLIT_SCALE));
            __half2 l23 = __float22half2_rn(
                make_float2((v.z - f23.x) * SPLIT_SCALE, (v.w - f23.y) * SPLIT_SCALE));
            uint32_t off = (uint32_t)(r * ROWP * 2 + j * 8);
            *(uint2*)(smem + XH_OFF + off) = make_uint2(h2u(h01), h2u(h23));
            *(uint2*)(smem + XL_OFF + off) = make_uint2(h2u(l01), h2u(l23));
        }
        #pragma unroll
        for (int p = 0; p < 4; p++) {
            int idx = tid + THREADS * p;
            int r = idx >> 3, j = idx & 7;
            uint32_t off = (uint32_t)(r * ROWP * 2 + j * 16);
            *(uint4*)(smem + WH_OFF + off) = whr[p];
            *(uint4*)(smem + WL_OFF + off) = wlr[p];
        }
    };

    issue_loads(0);
    store_stage();
    __syncthreads();

    for (int t = 0; t < NKT; t++) {
        if (t + 1 < NKT) issue_loads(t + 1);   // LDG in flight during mma

        #pragma unroll
        for (int k16 = 0; k16 < BK; k16 += 16) {
            uint32_t ah[4], al[4];
            ldsm_x4(ah, sbase + XH_OFF + a_byte + (uint32_t)k16 * 2);
            ldsm_x4(al, sbase + XL_OFF + a_byte + (uint32_t)k16 * 2);

            uint32_t bh[8][2], bl[8][2];
            #pragma unroll
            for (int p = 0; p < 4; p++) {
                uint32_t boff = (uint32_t)(p * 16 + b_rofs) * (ROWP * 2)
                              + (b_cofs + (uint32_t)k16) * 2;
                uint32_t rh[4], rl[4];
                ldsm_x4(rh, sbase + WH_OFF + boff);
                ldsm_x4(rl, sbase + WL_OFF + boff);
                bh[2 * p][0] = rh[0]; bh[2 * p][1] = rh[1];
                bh[2 * p + 1][0] = rh[2]; bh[2 * p + 1][1] = rh[3];
                bl[2 * p][0] = rl[0]; bl[2 * p][1] = rl[1];
                bl[2 * p + 1][0] = rl[2]; bl[2 * p + 1][1] = rl[3];
            }
            #pragma unroll
            for (int nt = 0; nt < 8; nt++) {
                mma16816(acc0[nt], ah, bh[nt]);
                mma16816(acc1[nt], ah, bl[nt]);
                mma16816(acc1[nt], al, bh[nt]);
            }
        }

        __syncthreads();                         // all reads of stage done
        if (t + 1 < NKT) {
            store_stage();                       // overwrite with tile t+1
            __syncthreads();
        }
    }

    // ---- epilogue: combine splits, add bias, write logits to smem ----
    float* ls = (float*)smem;                    // [64][65]
    #pragma unroll
    for (int nt = 0; nt < 8; nt++) {
        int n0 = nt * 8 + tg * 2;
        int r0 = wrow + g;
        float b0 = __ldg(bias + n0), b1 = __ldg(bias + n0 + 1);
        ls[r0 * (NEXP + 1) + n0]           = acc0[nt][0] + acc1[nt][0] * INV_SPLIT + b0;
        ls[r0 * (NEXP + 1) + n0 + 1]       = acc0[nt][1] + acc1[nt][1] * INV_SPLIT + b1;
        ls[(r0 + 8) * (NEXP + 1) + n0]     = acc0[nt][2] + acc1[nt][2] * INV_SPLIT + b0;
        ls[(r0 + 8) * (NEXP + 1) + n0 + 1] = acc0[nt][3] + acc1[nt][3] * INV_SPLIT + b1;
    }
    __syncthreads();

    // ---- per-token softmax + top-12 + flag (validated code) ----
    if (tid < BT) {
        float* row = ls + tid * (NEXP + 1);
        const int gt = tok0 + tid;

        float m = row[0];
        #pragma unroll
        for (int e = 1; e < NEXP; e++) m = fmaxf(m, row[e]);

        float s = 0.0f;
        #pragma unroll
        for (int e = 0; e < NEXP; e++) {
            float p = expf(row[e] - m);
            row[e] = p;
            s += p;
        }
        #pragma unroll
        for (int e = 0; e < NEXP; e++)
            row[e] = __fdiv_rn(row[e], s);

        float cv[NCAND];
        int   ci[NCAND];
        #pragma unroll
        for (int kq = 0; kq < NCAND; kq++) {
            float best = -1.0f;
            int   bi   = 0;
            for (int e = 0; e < NEXP; e++) {
                float p = row[e];
                if (p > best) { best = p; bi = e; }
            }
            cv[kq] = best;
            ci[kq] = bi;
            row[bi] = -1.0f;
        }

        int flag = 0;
        #pragma unroll
        for (int kq = 0; kq < NCAND - 1; kq++)
            if (cv[kq] - cv[kq + 1] < 2e-5f * cv[kq]) flag = 1;
        if (flag) {
            int slot = atomicAdd(&g_count, 1);
            g_list[slot] = gt;
        }

        #pragma unroll
        for (int e = 0; e < NEXP; e++) row[e] = 0.0f;
        #pragma unroll
        for (int kq = 0; kq < TOPK; kq++) row[ci[kq]] = cv[kq];

        #pragma unroll
        for (int kq = 0; kq < TOPK; kq++) {
            out[(size_t)gt * TOPK + kq]                       = cv[kq];
            out[(size_t)NTOK * TOPK + (size_t)gt * TOPK + kq] = (float)ci[kq];
        }
    }
    __syncthreads();

    float* gout = out + (size_t)NTOK * (2 * TOPK);
    for (int q = tid; q < BT * NEXP; q += THREADS) {
        int t = q >> 6;
        int e = q & 63;
        gout[(size_t)(tok0 + t) * NEXP + e] = ls[t * (NEXP + 1) + e];
    }
}

// ---- pass 2: one CTA per flagged token; 4 threads per expert, fp64 ----
__global__ void __launch_bounds__(256, 1)
refine_kernel(const float* __restrict__ x,
              const float* __restrict__ bias,
              const float* __restrict__ w,
              float* __restrict__ out)
{
    __shared__ float  xrow[DIM];
    __shared__ double lg[NEXP];

    const int tid  = threadIdx.x;
    const int lane = tid & 31;
    const int cnt  = g_count;

    for (int it = blockIdx.x; it < cnt; it += gridDim.x) {
        const int t = g_list[it];

        for (int k = tid; k < DIM; k += 256)
            xrow[k] = x[(size_t)t * DIM + k];
        __syncthreads();

        {
            const int e    = tid >> 2;
            const int part = tid & 3;
            const float* wr = w + (size_t)e * DIM;

            double s0 = 0.0, s1 = 0.0, s2 = 0.0, s3 = 0.0;
            for (int k = part * 4; k < DIM; k += 16) {
                s0 = fma((double)xrow[k + 0], (double)__ldg(wr + k + 0), s0);
                s1 = fma((double)xrow[k + 1], (double)__ldg(wr + k + 1), s1);
                s2 = fma((double)xrow[k + 2], (double)__ldg(wr + k + 2), s2);
                s3 = fma((double)xrow[k + 3], (double)__ldg(wr + k + 3), s3);
            }
            double s = (s0 + s1) + (s2 + s3);
            s += __shfl_down_sync(0xffffffffu, s, 2);
            s += __shfl_down_sync(0xffffffffu, s, 1);
            if ((lane & 3) == 0) lg[e] = s + (double)bias[e];
        }
        __syncthreads();

        if (tid == 0) {
            double m = lg[0];
            #pragma unroll
            for (int e = 1; e < NEXP; e++) m = fmax(m, lg[e]);
            double sum = 0.0;
            double pd[NEXP];
            #pragma unroll
            for (int e = 0; e < NEXP; e++) {
                pd[e] = exp(lg[e] - m);
                sum += pd[e];
            }
            double inv = 1.0 / sum;
            #pragma unroll
            for (int e = 0; e < NEXP; e++) pd[e] *= inv;

            double sv[NREF];
            int    si[NREF];
            for (int a = 0; a < NREF; a++) {
                double best = -1.0;
                int    bi   = 0;
                for (int e = 0; e < NEXP; e++)
                    if (pd[e] > best) { best = pd[e]; bi = e; }
                sv[a] = best;
                si[a] = bi;
                pd[bi] = -1.0;
            }

            for (int a = 0; a < NREF - 1; a++) {
                int di = si[a] - si[a + 1];
                if (di < 0) di = -di;
                if (sv[a] - sv[a + 1] < ULTRA_THIN * sv[a] && di >= SWAP_MIN_DIST) {
                    double tv = sv[a]; sv[a] = sv[a + 1]; sv[a + 1] = tv;
                    int    ti = si[a]; si[a] = si[a + 1]; si[a + 1] = ti;
                    a++;
                }
            }

            float* gout = out + (size_t)NTOK * (2 * TOPK) + (size_t)t * NEXP;
            #pragma unroll
            for (int e = 0; e < NEXP; e++) gout[e] = 0.0f;
            for (int a = 0; a < TOPK; a++) {
                float pv = (float)sv[a];
                out[(size_t)t * TOPK + a]                       = pv;
                out[(size_t)NTOK * TOPK + (size_t)t * TOPK + a] = (float)si[a];
                gout[si[a]] = pv;
            }
        }
        __syncthreads();
    }
}

extern "C" void kernel_launch(void* const* d_in, const int* in_sizes, int n_in,
                              void* d_out, int out_size)
{
    const float* x    = (const float*)d_in[0];
    const float* w    = (const float*)d_in[1];
    const float* bias = (const float*)d_in[2];
    float* out = (float*)d_out;

    cudaFuncSetAttribute(gate_kernel,
                         cudaFuncAttributeMaxDynamicSharedMemorySize, SMEM_TOTAL);

    wsplit_kernel<<<64, 256>>>(w);
    gate_kernel<<<NTOK / BT, THREADS, SMEM_TOTAL>>>(x, bias, out);
    refine_kernel<<<REFINE_CTAS, 256>>>(x, bias, w, out);
}